// round 10
// baseline (speedup 1.0000x reference)
#include <cuda_runtime.h>
#include <cuda_fp16.h>

#define BATCH   32768
#define PIECES  32
#define NNZ     (BATCH * PIECES)
#define FT      512
#define NF      768
#define CHUNK   64               // output channels per chunk
#define NCHUNK  (FT / CHUNK)     // 8
#define ROWB    (CHUNK * 2)      // 128 bytes per feature row in smem
#define NBLK    37               // blocks per chunk: 8*37 = 296 = 2 per SM

// ---------------- device scratch (no allocations allowed) ----------------
__device__ __half g_Wt[NF * FT];          // transposed fp16 weights [feat][out]
__device__ float  g_partial[NCHUNK * BATCH];

// ---------------- prep: tiled transpose ft_w [512,768] -> [768,512] fp16 --
__global__ void prep_w(const float* __restrict__ ft_w) {
    __shared__ float tile[32][33];
    const int tx = threadIdx.x, ty = threadIdx.y;       // 32 x 8
    const int fb = blockIdx.x * 32;                     // feature tile base
    const int kb = blockIdx.y * 32;                     // channel tile base
    #pragma unroll
    for (int i = 0; i < 32; i += 8)
        tile[ty + i][tx] = ft_w[(kb + ty + i) * NF + fb + tx];   // coalesced in f
    __syncthreads();
    #pragma unroll
    for (int i = 0; i < 32; i += 8)
        g_Wt[(fb + ty + i) * FT + kb + tx] = __float2half(tile[tx][ty + i]);
}

// ---------------- main: gather-accumulate from smem-resident W chunk -----
// CHUNK=64 half-warp split: lanes 0-15 gather the STM row, lanes 16-31 the
// NSTM row -> ONE LDS.64 per piece covers both 128-B rows (256 B = 2 crossbar
// phases, the byte minimum). Per piece: 1 SHFL + 1 LDS.64.
// pk layout: bits [7,17) = cs*128, bits [17,27) = cn (so >>10 puts cn*128 in
// bits [7,17)). Extract mask 0x1FF80 = bits 7..16 (col*128 max 98176, 17 bits).
__global__ void __launch_bounds__(512, 2)
main_k(const int* __restrict__ stm32, const int* __restrict__ nstm32,
       const float* __restrict__ vals,
       const float* __restrict__ ft_b, const float* __restrict__ out_w) {
    extern __shared__ __half sW[];   // [NF][CHUNK] fp16 = 96 KB
    const int chunk = blockIdx.y;
    const int tid = threadIdx.x;

    // stage W chunk: 6144 uint4 copies
    {
        uint4* dst = (uint4*)sW;
        for (int i = tid; i < NF * (CHUNK / 8); i += blockDim.x) {
            int f = i >> 3;          // feature
            int q = i & 7;           // 16B quad within 128-B row
            dst[i] = ((const uint4*)(g_Wt + f * FT + chunk * CHUNK))[q];
        }
    }
    __syncthreads();

    const int warp = tid >> 5, lane = tid & 31;
    const int gw = blockIdx.x * (blockDim.x >> 5) + warp;
    const int stride = gridDim.x * (blockDim.x >> 5);

    // dtype sniff: row 0 of indices is repeat(arange(B),32); an int32 view has
    // [64]=1,[65]=0 iff little-endian int64, [64]=2,[65]=2 iff int32.
    const bool is64 = (stm32[64] == 1 && stm32[65] == 0);

    const int side = lane >> 4;                 // 0 = stm, 1 = nstm
    const int li   = lane & 15;                 // lane within half
    const int sh   = side * 10;                 // extract shift for my side
    const char* sbase = (const char*)sW + li * 8;   // my 8B within a row

    // epilogue coefficients: this lane owns 4 channels of one side
    const int ch = chunk * CHUNK + li * 4;
    const float4 bb = *(const float4*)(ft_b + ch);
    const float4 ww = *(const float4*)(out_w + side * FT + ch);

    const __half2 hz = __float2half2_rn(0.f);

    for (int b = gw; b < BATCH; b += stride) {
        const int base = b * PIECES + lane;

        // direct index/value loads (no prep pass)
        int cs, cn;
        if (is64) {
            cs = stm32[2 * (NNZ + base)];      // low word of int64 col
            cn = nstm32[2 * (NNZ + base)];
        } else {
            cs = stm32[NNZ + base];
            cn = nstm32[NNZ + base];
        }
        const float v = vals[base];
        const int pk = (cs << 7) | (cn << 17);   // pre-shifted: col*ROWB packed
        const bool ones = __all_sync(0xffffffffu, v == 1.0f);

        // split accumulator banks (even/odd pieces): 4 half2 total
        __half2 a0 = hz, a1 = hz, c0 = hz, c1 = hz;

        if (ones) {
            #pragma unroll
            for (int j = 0; j < PIECES; j++) {
                int p = __shfl_sync(0xffffffffu, pk, j);
                uint2 d = *(const uint2*)(sbase + ((p >> sh) & 0x1FF80));
                __half2 h0 = *(__half2*)&d.x;
                __half2 h1 = *(__half2*)&d.y;
                if (j & 1) { c0 = __hadd2(c0, h0); c1 = __hadd2(c1, h1); }
                else       { a0 = __hadd2(a0, h0); a1 = __hadd2(a1, h1); }
            }
        } else {
            const unsigned vv = (unsigned)__half_as_ushort(__float2half(v));
            #pragma unroll
            for (int j = 0; j < PIECES; j++) {
                int p = __shfl_sync(0xffffffffu, pk, j);
                unsigned vj = __shfl_sync(0xffffffffu, vv, j);
                __half2 v2 = __half2half2(__ushort_as_half((unsigned short)vj));
                uint2 d = *(const uint2*)(sbase + ((p >> sh) & 0x1FF80));
                __half2 h0 = *(__half2*)&d.x;
                __half2 h1 = *(__half2*)&d.y;
                if (j & 1) { c0 = __hfma2(h0, v2, c0); c1 = __hfma2(h1, v2, c1); }
                else       { a0 = __hfma2(h0, v2, a0); a1 = __hfma2(h1, v2, a1); }
            }
        }

        // combine banks in fp32
        float2 f0a = __half22float2(a0), f0c = __half22float2(c0);
        float2 f1a = __half22float2(a1), f1c = __half22float2(c1);

        float r = 0.f;
        r += __saturatef(f0a.x + f0c.x + bb.x) * ww.x;
        r += __saturatef(f0a.y + f0c.y + bb.y) * ww.y;
        r += __saturatef(f1a.x + f1c.x + bb.z) * ww.z;
        r += __saturatef(f1a.y + f1c.y + bb.w) * ww.w;

        // butterfly over 32 lanes sums 16 li x 2 sides
        #pragma unroll
        for (int d = 16; d > 0; d >>= 1)
            r += __shfl_xor_sync(0xffffffffu, r, d);

        if (lane == 0) g_partial[chunk * BATCH + b] = r;
    }
}

// ---------------- epilogue: sum partials + sigmoid (float4) --------------
__global__ void epi_k(const float* __restrict__ out_b, float* __restrict__ out) {
    int t = blockIdx.x * blockDim.x + threadIdx.x;    // 8192 threads, 4 b each
    if (t < BATCH / 4) {
        const float bias = out_b[0];
        float4 s = ((const float4*)g_partial)[t];
        #pragma unroll
        for (int c = 1; c < NCHUNK; c++) {
            float4 p = ((const float4*)(g_partial + c * BATCH))[t];
            s.x += p.x; s.y += p.y; s.z += p.z; s.w += p.w;
        }
        float4 o;
        o.x = 1.f / (1.f + __expf(-(s.x + bias)));
        o.y = 1.f / (1.f + __expf(-(s.y + bias)));
        o.z = 1.f / (1.f + __expf(-(s.z + bias)));
        o.w = 1.f / (1.f + __expf(-(s.w + bias)));
        ((float4*)out)[t] = o;
    }
}

// ---------------- launch --------------------------------------------------
extern "C" void kernel_launch(void* const* d_in, const int* in_sizes, int n_in,
                              void* d_out, int out_size) {
    // Fixed leading inputs (dict order): stm_indices, nstm_indices, values.
    const int*   stm  = (const int*)d_in[0];   // [2, NNZ] int32 or int64 (sniffed)
    const int*   nstm = (const int*)d_in[1];
    const float* vals = (const float*)d_in[2];

    // Trailing inputs mapped by element count ("size" may or may not be a
    // real buffer). out_b is the LAST size-1 entry (dict order: size < out_b).
    const float* ft_w  = 0;
    const float* ft_b  = 0;
    const float* out_w = 0;
    const float* out_b = 0;
    for (int i = 3; i < n_in; i++) {
        int s = in_sizes[i];
        if      (s == NF * FT) ft_w  = (const float*)d_in[i];
        else if (s == FT)      ft_b  = (const float*)d_in[i];
        else if (s == 2 * FT)  out_w = (const float*)d_in[i];
        else if (s == 1)       out_b = (const float*)d_in[i];  // last wins
    }
    float* out = (float*)d_out;                  // [B, 1] float32

    prep_w<<<dim3(NF / 32, FT / 32), dim3(32, 8)>>>(ft_w);

    const int SMEM = NF * CHUNK * 2;   // 96 KB
    cudaFuncSetAttribute(main_k, cudaFuncAttributeMaxDynamicSharedMemorySize, SMEM);
    main_k<<<dim3(NBLK, NCHUNK), 512, SMEM>>>(stm, nstm, vals, ft_b, out_w);

    epi_k<<<(BATCH / 4 + 127) / 128, 128>>>(out_b, out);
}

// round 11
// speedup vs baseline: 1.0637x; 1.0637x over previous
#include <cuda_runtime.h>
#include <cuda_fp16.h>

#define BATCH   32768
#define PIECES  32
#define NNZ     (BATCH * PIECES)
#define FT      512
#define NF      768
#define CHUNK   128              // output channels per chunk (looped in time)
#define NCHUNK  (FT / CHUNK)     // 4
#define NCTA    148              // one CTA per SM
#define NWARP   16               // warps per CTA
#define GWS     (NCTA * NWARP)   // 2368 global warps
#define MAXSLOT 14               // ceil(BATCH / GWS)

// ---------------- device scratch (no allocations allowed) ----------------
__device__ __half g_Wt[NF * FT];          // transposed fp16 weights [feat][out]

// ---------------- prep: tiled transpose ft_w [512,768] -> [768,512] fp16 --
__global__ void prep_w(const float* __restrict__ ft_w) {
    __shared__ float tile[32][33];
    const int tx = threadIdx.x, ty = threadIdx.y;       // 32 x 8
    const int fb = blockIdx.x * 32;                     // feature tile base
    const int kb = blockIdx.y * 32;                     // channel tile base
    #pragma unroll
    for (int i = 0; i < 32; i += 8)
        tile[ty + i][tx] = ft_w[(kb + ty + i) * NF + fb + tx];   // coalesced in f
    __syncthreads();
    #pragma unroll
    for (int i = 0; i < 32; i += 8)
        g_Wt[(fb + ty + i) * FT + kb + tx] = __float2half(tile[tx][ty + i]);
}

// ---------------- fused main: 4 chunk phases in time + sigmoid epilogue --
// Inner loop identical to the proven R6 kernel (1 SHFL + 2 LDS.64 per piece,
// warp-wide uint2 row reads). Per-position logit accumulates in smem across
// chunk phases; bias + sigmoid + store happen in-kernel (no epi_k, no
// g_partial HBM round-trip).
__global__ void __launch_bounds__(512, 1)
main_k(const int* __restrict__ stm32, const int* __restrict__ nstm32,
       const float* __restrict__ vals,
       const float* __restrict__ ft_b, const float* __restrict__ out_w,
       const float* __restrict__ out_b, float* __restrict__ out) {
    extern __shared__ __half sW[];                 // [NF][CHUNK] fp16 = 192 KB
    float* slog = (float*)(sW + NF * CHUNK);       // [NWARP][MAXSLOT] logits

    const int tid = threadIdx.x;
    const int warp = tid >> 5, lane = tid & 31;
    const int gw = blockIdx.x * NWARP + warp;      // 0..2367

    // dtype sniff: row 0 of indices is repeat(arange(B),32); an int32 view has
    // [64]=1,[65]=0 iff little-endian int64, [64]=2,[65]=2 iff int32.
    const bool is64 = (stm32[64] == 1 && stm32[65] == 0);

    const char* sbase = (const char*)sW + lane * 8;   // lane's 8B within a row
    const __half2 hz = __float2half2_rn(0.f);

    for (int chunk = 0; chunk < NCHUNK; chunk++) {
        __syncthreads();   // previous phase's readers done before overwrite
        // stage W chunk: 12288 uint4 copies (L2-resident source)
        {
            uint4* dst = (uint4*)sW;
            for (int i = tid; i < NF * (CHUNK / 8); i += blockDim.x) {
                int f = i >> 4;          // feature
                int q = i & 15;          // 16B quad within 256-B row
                dst[i] = ((const uint4*)(g_Wt + f * FT + chunk * CHUNK))[q];
            }
        }
        __syncthreads();

        // epilogue coefficients for this lane's 4 channels of this chunk
        const int ch = chunk * CHUNK + lane * 4;
        const float4 bb = *(const float4*)(ft_b + ch);
        const float4 ws = *(const float4*)(out_w + ch);
        const float4 wn = *(const float4*)(out_w + FT + ch);

        int k = 0;
        for (int b = gw; b < BATCH; b += GWS, k++) {
            const int base = b * PIECES + lane;

            // direct index/value loads (no prep pass)
            int cs, cn;
            if (is64) {
                cs = stm32[2 * (NNZ + base)];      // low word of int64 col
                cn = nstm32[2 * (NNZ + base)];
            } else {
                cs = stm32[NNZ + base];
                cn = nstm32[NNZ + base];
            }
            const float v = vals[base];
            const int pk = (cs << 8) | (cn << 18);   // byte offsets packed
            const bool ones = __all_sync(0xffffffffu, v == 1.0f);

            // split accumulator banks (even/odd pieces)
            __half2 aS0a = hz, aS1a = hz, aS0b = hz, aS1b = hz;
            __half2 aN0a = hz, aN1a = hz, aN0b = hz, aN1b = hz;

            if (ones) {
                #pragma unroll
                for (int j = 0; j < PIECES; j++) {
                    int p = __shfl_sync(0xffffffffu, pk, j);
                    uint2 dS = *(const uint2*)(sbase + (p & 0x3FF00));
                    uint2 dN = *(const uint2*)(sbase + ((p >> 10) & 0x3FF00));
                    __half2 s0 = *(__half2*)&dS.x;
                    __half2 s1 = *(__half2*)&dS.y;
                    __half2 n0 = *(__half2*)&dN.x;
                    __half2 n1 = *(__half2*)&dN.y;
                    if (j & 1) {
                        aS0b = __hadd2(aS0b, s0); aS1b = __hadd2(aS1b, s1);
                        aN0b = __hadd2(aN0b, n0); aN1b = __hadd2(aN1b, n1);
                    } else {
                        aS0a = __hadd2(aS0a, s0); aS1a = __hadd2(aS1a, s1);
                        aN0a = __hadd2(aN0a, n0); aN1a = __hadd2(aN1a, n1);
                    }
                }
            } else {
                const unsigned vv = (unsigned)__half_as_ushort(__float2half(v));
                #pragma unroll
                for (int j = 0; j < PIECES; j++) {
                    int p = __shfl_sync(0xffffffffu, pk, j);
                    unsigned vj = __shfl_sync(0xffffffffu, vv, j);
                    __half2 v2 = __half2half2(__ushort_as_half((unsigned short)vj));
                    uint2 dS = *(const uint2*)(sbase + (p & 0x3FF00));
                    uint2 dN = *(const uint2*)(sbase + ((p >> 10) & 0x3FF00));
                    __half2 s0 = *(__half2*)&dS.x;
                    __half2 s1 = *(__half2*)&dS.y;
                    __half2 n0 = *(__half2*)&dN.x;
                    __half2 n1 = *(__half2*)&dN.y;
                    if (j & 1) {
                        aS0b = __hfma2(s0, v2, aS0b); aS1b = __hfma2(s1, v2, aS1b);
                        aN0b = __hfma2(n0, v2, aN0b); aN1b = __hfma2(n1, v2, aN1b);
                    } else {
                        aS0a = __hfma2(s0, v2, aS0a); aS1a = __hfma2(s1, v2, aS1a);
                        aN0a = __hfma2(n0, v2, aN0a); aN1a = __hfma2(n1, v2, aN1a);
                    }
                }
            }

            // combine banks in fp32
            float2 fS0a = __half22float2(aS0a), fS0b = __half22float2(aS0b);
            float2 fS1a = __half22float2(aS1a), fS1b = __half22float2(aS1b);
            float2 fN0a = __half22float2(aN0a), fN0b = __half22float2(aN0b);
            float2 fN1a = __half22float2(aN1a), fN1b = __half22float2(aN1b);

            float s0 = fS0a.x + fS0b.x, s1 = fS0a.y + fS0b.y;
            float s2 = fS1a.x + fS1b.x, s3 = fS1a.y + fS1b.y;
            float n0 = fN0a.x + fN0b.x, n1 = fN0a.y + fN0b.y;
            float n2 = fN1a.x + fN1b.x, n3 = fN1a.y + fN1b.y;

            float r = 0.f;
            r += __saturatef(s0 + bb.x) * ws.x;
            r += __saturatef(s1 + bb.y) * ws.y;
            r += __saturatef(s2 + bb.z) * ws.z;
            r += __saturatef(s3 + bb.w) * ws.w;
            r += __saturatef(n0 + bb.x) * wn.x;
            r += __saturatef(n1 + bb.y) * wn.y;
            r += __saturatef(n2 + bb.z) * wn.z;
            r += __saturatef(n3 + bb.w) * wn.w;

            #pragma unroll
            for (int d = 16; d > 0; d >>= 1)
                r += __shfl_xor_sync(0xffffffffu, r, d);

            if (lane == 0) {
                float* slot = slog + warp * MAXSLOT + k;
                *slot = (chunk == 0) ? r : (*slot + r);
            }
        }
    }

    // in-kernel epilogue: bias + sigmoid + store (each warp owns its slots)
    __syncwarp();
    const int nslots = (BATCH - gw + GWS - 1) / GWS;   // 13 or 14
    if (lane < nslots) {
        float s = slog[warp * MAXSLOT + lane] + out_b[0];
        out[gw + lane * GWS] = 1.f / (1.f + __expf(-s));
    }
}

// ---------------- launch --------------------------------------------------
extern "C" void kernel_launch(void* const* d_in, const int* in_sizes, int n_in,
                              void* d_out, int out_size) {
    // Fixed leading inputs (dict order): stm_indices, nstm_indices, values.
    const int*   stm  = (const int*)d_in[0];   // [2, NNZ] int32 or int64 (sniffed)
    const int*   nstm = (const int*)d_in[1];
    const float* vals = (const float*)d_in[2];

    // Trailing inputs mapped by element count ("size" may or may not be a
    // real buffer). out_b is the LAST size-1 entry (dict order: size < out_b).
    const float* ft_w  = 0;
    const float* ft_b  = 0;
    const float* out_w = 0;
    const float* out_b = 0;
    for (int i = 3; i < n_in; i++) {
        int s = in_sizes[i];
        if      (s == NF * FT) ft_w  = (const float*)d_in[i];
        else if (s == FT)      ft_b  = (const float*)d_in[i];
        else if (s == 2 * FT)  out_w = (const float*)d_in[i];
        else if (s == 1)       out_b = (const float*)d_in[i];  // last wins
    }
    float* out = (float*)d_out;                  // [B, 1] float32

    prep_w<<<dim3(NF / 32, FT / 32), dim3(32, 8)>>>(ft_w);

    const int SMEM = NF * CHUNK * 2 + NWARP * MAXSLOT * 4 + 128;  // ~193 KB
    cudaFuncSetAttribute(main_k, cudaFuncAttributeMaxDynamicSharedMemorySize, SMEM);
    main_k<<<NCTA, 512, SMEM>>>(stm, nstm, vals, ft_b, out_w, out_b, out);
}

// round 12
// speedup vs baseline: 1.2256x; 1.1522x over previous
#include <cuda_runtime.h>
#include <cuda_fp16.h>

#define BATCH   32768
#define PIECES  32
#define NNZ     (BATCH * PIECES)
#define FT      512
#define NF      768
#define CHUNK   128              // output channels per chunk
#define NCHUNK  (FT / CHUNK)     // 4
#define NBLK    37               // blocks per chunk: 4*37 = 148 = #SMs

#define TPB_PREP     256
#define TRANS_BLOCKS (NF / 32 * FT / 32)         // 24*16 = 384
#define PACK_BLOCKS  (NNZ / TPB_PREP)            // 4096

// ---------------- device scratch (no allocations allowed) ----------------
__device__ __half g_Wt[NF * FT];          // transposed fp16 weights [feat][out]
__device__ int    g_pack[NNZ];            // (cs<<8) | (cn<<18)
__device__ float  g_partial[NCHUNK * BATCH];

// ---------------- prep: transpose W (fp16) + pack indices, one kernel ----
__global__ void prep_k(const float* __restrict__ ft_w,
                       const int* __restrict__ stm32,
                       const int* __restrict__ nstm32) {
    const int bid = blockIdx.x, tid = threadIdx.x;
    if (bid < TRANS_BLOCKS) {
        // tiled transpose ft_w [512,768] -> g_Wt [768,512] fp16
        __shared__ float tile[32][33];
        const int tx = tid & 31, ty = tid >> 5;          // 32 x 8
        const int fb = (bid % (NF / 32)) * 32;           // feature tile base
        const int kb = (bid / (NF / 32)) * 32;           // channel tile base
        #pragma unroll
        for (int i = 0; i < 32; i += 8)
            tile[ty + i][tx] = ft_w[(kb + ty + i) * NF + fb + tx];
        __syncthreads();
        #pragma unroll
        for (int i = 0; i < 32; i += 8)
            g_Wt[(fb + ty + i) * FT + kb + tx] = __float2half(tile[tx][ty + i]);
    } else {
        // pack columns. dtype sniff: row 0 is repeat(arange(B),32): int32 view
        // [64]=1,[65]=0 iff little-endian int64; [64]=2,[65]=2 iff int32.
        const int i = (bid - TRANS_BLOCKS) * TPB_PREP + tid;
        if (i < NNZ) {
            const bool is64 = (stm32[64] == 1 && stm32[65] == 0);
            int cs, cn;
            if (is64) {
                cs = stm32[2 * (NNZ + i)];      // low word of int64 col
                cn = nstm32[2 * (NNZ + i)];
            } else {
                cs = stm32[NNZ + i];
                cn = nstm32[NNZ + i];
            }
            g_pack[i] = (cs << 8) | (cn << 18);
        }
    }
}

// ---------------- main: gather-accumulate from smem-resident W chunk -----
// R6 proven loop (warp-wide uint2 row reads, one packed SHFL per piece),
// plus: precomputed g_pack (1 LDG.32 per position) and next-position
// prefetch of pk/v to hide index-load latency under the gather.
__global__ void __launch_bounds__(512, 1)
main_k(const float* __restrict__ vals,
       const float* __restrict__ ft_b, const float* __restrict__ out_w) {
    extern __shared__ __half sW[];   // [NF][CHUNK] fp16 = 192 KB
    const int chunk = blockIdx.y;
    const int tid = threadIdx.x;

    // stage W chunk: 12288 uint4 copies
    {
        uint4* dst = (uint4*)sW;
        for (int i = tid; i < NF * (CHUNK / 8); i += blockDim.x) {
            int f = i >> 4;          // feature
            int q = i & 15;          // 16B quad within 256-B row
            dst[i] = ((const uint4*)(g_Wt + f * FT + chunk * CHUNK))[q];
        }
    }
    __syncthreads();

    const int warp = tid >> 5, lane = tid & 31;
    const int gw = blockIdx.x * (blockDim.x >> 5) + warp;
    const int stride = gridDim.x * (blockDim.x >> 5);

    const char* sbase = (const char*)sW + lane * 8;   // lane's 8B within a row

    // loop-invariant epilogue coefficients for this lane's 4 channels
    const int ch = chunk * CHUNK + lane * 4;
    const float4 bb = *(const float4*)(ft_b + ch);
    const float4 ws = *(const float4*)(out_w + ch);
    const float4 wn = *(const float4*)(out_w + FT + ch);

    const __half2 hz = __float2half2_rn(0.f);

    int b = gw;
    int   pk = (b < BATCH) ? g_pack[b * PIECES + lane] : 0;
    float v  = (b < BATCH) ? vals[b * PIECES + lane] : 1.f;

    while (b < BATCH) {
        // prefetch next position's pack/value (hidden under this gather)
        const int bn = b + stride;
        int pk_n = 0; float v_n = 1.f;
        if (bn < BATCH) {
            pk_n = g_pack[bn * PIECES + lane];
            v_n  = vals[bn * PIECES + lane];
        }

        const bool ones = __all_sync(0xffffffffu, v == 1.0f);

        // split accumulator banks (even/odd pieces)
        __half2 aS0a = hz, aS1a = hz, aS0b = hz, aS1b = hz;
        __half2 aN0a = hz, aN1a = hz, aN0b = hz, aN1b = hz;

        if (ones) {
            #pragma unroll
            for (int j = 0; j < PIECES; j++) {
                int p = __shfl_sync(0xffffffffu, pk, j);
                uint2 dS = *(const uint2*)(sbase + (p & 0x3FF00));
                uint2 dN = *(const uint2*)(sbase + ((p >> 10) & 0x3FF00));
                __half2 s0 = *(__half2*)&dS.x;
                __half2 s1 = *(__half2*)&dS.y;
                __half2 n0 = *(__half2*)&dN.x;
                __half2 n1 = *(__half2*)&dN.y;
                if (j & 1) {
                    aS0b = __hadd2(aS0b, s0); aS1b = __hadd2(aS1b, s1);
                    aN0b = __hadd2(aN0b, n0); aN1b = __hadd2(aN1b, n1);
                } else {
                    aS0a = __hadd2(aS0a, s0); aS1a = __hadd2(aS1a, s1);
                    aN0a = __hadd2(aN0a, n0); aN1a = __hadd2(aN1a, n1);
                }
            }
        } else {
            const unsigned vv = (unsigned)__half_as_ushort(__float2half(v));
            #pragma unroll
            for (int j = 0; j < PIECES; j++) {
                int p = __shfl_sync(0xffffffffu, pk, j);
                unsigned vj = __shfl_sync(0xffffffffu, vv, j);
                __half2 v2 = __half2half2(__ushort_as_half((unsigned short)vj));
                uint2 dS = *(const uint2*)(sbase + (p & 0x3FF00));
                uint2 dN = *(const uint2*)(sbase + ((p >> 10) & 0x3FF00));
                __half2 s0 = *(__half2*)&dS.x;
                __half2 s1 = *(__half2*)&dS.y;
                __half2 n0 = *(__half2*)&dN.x;
                __half2 n1 = *(__half2*)&dN.y;
                if (j & 1) {
                    aS0b = __hfma2(s0, v2, aS0b); aS1b = __hfma2(s1, v2, aS1b);
                    aN0b = __hfma2(n0, v2, aN0b); aN1b = __hfma2(n1, v2, aN1b);
                } else {
                    aS0a = __hfma2(s0, v2, aS0a); aS1a = __hfma2(s1, v2, aS1a);
                    aN0a = __hfma2(n0, v2, aN0a); aN1a = __hfma2(n1, v2, aN1a);
                }
            }
        }

        // combine banks in fp32
        float2 fS0a = __half22float2(aS0a), fS0b = __half22float2(aS0b);
        float2 fS1a = __half22float2(aS1a), fS1b = __half22float2(aS1b);
        float2 fN0a = __half22float2(aN0a), fN0b = __half22float2(aN0b);
        float2 fN1a = __half22float2(aN1a), fN1b = __half22float2(aN1b);

        float s0 = fS0a.x + fS0b.x, s1 = fS0a.y + fS0b.y;
        float s2 = fS1a.x + fS1b.x, s3 = fS1a.y + fS1b.y;
        float n0 = fN0a.x + fN0b.x, n1 = fN0a.y + fN0b.y;
        float n2 = fN1a.x + fN1b.x, n3 = fN1a.y + fN1b.y;

        float r = 0.f;
        r += __saturatef(s0 + bb.x) * ws.x;
        r += __saturatef(s1 + bb.y) * ws.y;
        r += __saturatef(s2 + bb.z) * ws.z;
        r += __saturatef(s3 + bb.w) * ws.w;
        r += __saturatef(n0 + bb.x) * wn.x;
        r += __saturatef(n1 + bb.y) * wn.y;
        r += __saturatef(n2 + bb.z) * wn.z;
        r += __saturatef(n3 + bb.w) * wn.w;

        #pragma unroll
        for (int d = 16; d > 0; d >>= 1)
            r += __shfl_xor_sync(0xffffffffu, r, d);

        if (lane == 0) g_partial[chunk * BATCH + b] = r;

        b = bn; pk = pk_n; v = v_n;
    }
}

// ---------------- epilogue: sum partials + sigmoid (float4) --------------
__global__ void epi_k(const float* __restrict__ out_b, float* __restrict__ out) {
    int t = blockIdx.x * blockDim.x + threadIdx.x;    // 8192 threads, 4 b each
    if (t < BATCH / 4) {
        const float bias = out_b[0];
        float4 s = ((const float4*)g_partial)[t];
        #pragma unroll
        for (int c = 1; c < NCHUNK; c++) {
            float4 p = ((const float4*)(g_partial + c * BATCH))[t];
            s.x += p.x; s.y += p.y; s.z += p.z; s.w += p.w;
        }
        float4 o;
        o.x = 1.f / (1.f + __expf(-(s.x + bias)));
        o.y = 1.f / (1.f + __expf(-(s.y + bias)));
        o.z = 1.f / (1.f + __expf(-(s.z + bias)));
        o.w = 1.f / (1.f + __expf(-(s.w + bias)));
        ((float4*)out)[t] = o;
    }
}

// ---------------- launch --------------------------------------------------
extern "C" void kernel_launch(void* const* d_in, const int* in_sizes, int n_in,
                              void* d_out, int out_size) {
    // Fixed leading inputs (dict order): stm_indices, nstm_indices, values.
    const int*   stm  = (const int*)d_in[0];   // [2, NNZ] int32 or int64 (sniffed)
    const int*   nstm = (const int*)d_in[1];
    const float* vals = (const float*)d_in[2];

    // Trailing inputs mapped by element count ("size" may or may not be a
    // real buffer). out_b is the LAST size-1 entry (dict order: size < out_b).
    const float* ft_w  = 0;
    const float* ft_b  = 0;
    const float* out_w = 0;
    const float* out_b = 0;
    for (int i = 3; i < n_in; i++) {
        int s = in_sizes[i];
        if      (s == NF * FT) ft_w  = (const float*)d_in[i];
        else if (s == FT)      ft_b  = (const float*)d_in[i];
        else if (s == 2 * FT)  out_w = (const float*)d_in[i];
        else if (s == 1)       out_b = (const float*)d_in[i];  // last wins
    }
    float* out = (float*)d_out;                  // [B, 1] float32

    prep_k<<<TRANS_BLOCKS + PACK_BLOCKS, TPB_PREP>>>(ft_w, stm, nstm);

    const int SMEM = NF * CHUNK * 2;   // 192 KB
    cudaFuncSetAttribute(main_k, cudaFuncAttributeMaxDynamicSharedMemorySize, SMEM);
    main_k<<<dim3(NBLK, NCHUNK), 512, SMEM>>>(vals, ft_b, out_w);

    epi_k<<<(BATCH / 4 + 127) / 128, 128>>>(out_b, out);
}